// round 10
// baseline (speedup 1.0000x reference)
#include <cuda_runtime.h>

// XdGate on site INDEX=3 of an L=8 qutrit (D=3) state vector, N = 3^8 = 6561.
//
// U = I x I x I x M x I x I x I x I with M|i> = |(3-i) mod 3> — a pure
// permutation of the site-3 trit (stride 3^4 = 81):
//   t=0 -> delta 0, t=1 -> +81, t=2 -> -81 (element offsets).
//
// TERMINAL KERNEL (session closure). Nine rounds of evidence:
//   - ncu kernel time 3.97-4.54us across ALL structural variants
//     (grid 7/9/26/27, scalar/vec4 stores, div vs div-free trit, 1D/2D/3D
//     blocks, guard/no-guard) — one noise cloud, +-0.3us.
//   - harness graph-replay time 5.02-6.08us, with an identical binary
//     measuring both 5.02 and 5.63us -> +-0.6us harness noise.
//   - issue <=10%, DRAM 0.1%, ALU/FMA 0.0%: the body does not register;
//     duration = fixed launch/ramp/drain at unboosted DVFS clocks.
// Conclusion: single-mandatory-launch overhead floor. This is the variant
// with the best recorded harness time (5.024us) and the simplest SASS.
// Ruled out with evidence/structure: 16B vectorized access (src/dst differ
// by 81 elems = 4B mod 16 -> misaligned), memcpy decomposition (>=3 graph
// nodes > 1 kernel node), TMA/smem staging (adds cost to 52KB of traffic).

static constexpr int STRIDE = 81;   // 3^4

__global__ __launch_bounds__(243) void xd_gate_kernel(
    const float* __restrict__ x, float* __restrict__ out) {
    int idx = blockIdx.x * 243 + threadIdx.x;   // exact cover of [0, 6561)

    int t = (idx / STRIDE) % 3;
    // delta multiplier: t=0 -> 0, t=1 -> +1, t=2 -> -1
    int d = (t == 1) - (t == 2);
    out[idx] = x[idx + d * STRIDE];
}

extern "C" void kernel_launch(void* const* d_in, const int* in_sizes, int n_in,
                              void* d_out, int out_size) {
    const float* x = (const float*)d_in[0];   // [6561, 1] float32
    // d_in[1] is M [3,3] — permutation baked in.
    float* out = (float*)d_out;

    xd_gate_kernel<<<27, 243>>>(x, out);      // 27 * 243 = 6561 exactly
}